// round 4
// baseline (speedup 1.0000x reference)
#include <cuda_runtime.h>
#include <cuda_bf16.h>
#include <cstdint>

// ===================== problem constants =====================
#define BSZ   8192
#define DDIM  512
#define NCLS  100
#define INV_T 14.285714285714286f   // 1/0.07
#define SHIFT 14.285714285714286f   // max possible logit (|e|=1)
#define LOG2E 1.4426950408889634f
#define C1F   (INV_T * LOG2E)
#define C2F   (SHIFT * LOG2E)

#define NTILE 64                    // 8192 / 128
#define PAIR_CAP (1 << 22)          // 4M pair records (expected ~331k)

// ===================== device scratch (no allocs allowed) =====================
// uint4 backing guarantees 16B alignment (required by cp.async.16 / vector stores)
__device__ uint4    g_ebf_raw[BSZ * DDIM * 2 / 16];   // 8 MB bf16 embeddings
#define g_ebf ((__nv_bfloat16*)g_ebf_raw)
__device__ float    g_rowsum[BSZ];
__device__ float    g_basev[BSZ];
__device__ float    g_invc[BSZ];
__device__ double   g_loss;
__device__ int      g_cls_cnt[NCLS];
__device__ int      g_npair;
__device__ uint32_t g_pk[PAIR_CAP];           // (i<<13)|j, i<j, same label
__device__ float    g_pl[PAIR_CAP];           // raw dot for that pair

// ===================== small helpers =====================
__device__ __forceinline__ uint32_t smem_u32(const void* p) {
    uint32_t a;
    asm("{ .reg .u64 t; cvta.to.shared.u64 t, %1; cvt.u32.u64 %0, t; }" : "=r"(a) : "l"(p));
    return a;
}
__device__ __forceinline__ float fast_ex2(float x) {
    float y; asm("ex2.approx.ftz.f32 %0, %1;" : "=f"(y) : "f"(x)); return y;
}
__device__ __forceinline__ void cp_async16(uint32_t sad, const void* gad) {
    asm volatile("cp.async.cg.shared.global [%0], [%1], 16;" :: "r"(sad), "l"(gad) : "memory");
}
__device__ __forceinline__ void ldsm_x4(uint32_t* r, uint32_t addr) {
    asm volatile("ldmatrix.sync.aligned.m8n8.x4.shared.b16 {%0,%1,%2,%3}, [%4];"
                 : "=r"(r[0]), "=r"(r[1]), "=r"(r[2]), "=r"(r[3]) : "r"(addr));
}
__device__ __forceinline__ void ldsm_x2(uint32_t* r, uint32_t addr) {
    asm volatile("ldmatrix.sync.aligned.m8n8.x2.shared.b16 {%0,%1}, [%2];"
                 : "=r"(r[0]), "=r"(r[1]) : "r"(addr));
}
__device__ __forceinline__ void mma16816(float* d, const uint32_t* a, const uint32_t* b) {
    asm volatile("mma.sync.aligned.m16n8k16.row.col.f32.bf16.bf16.f32 "
                 "{%0,%1,%2,%3}, {%4,%5,%6,%7}, {%8,%9}, {%0,%1,%2,%3};"
                 : "+f"(d[0]), "+f"(d[1]), "+f"(d[2]), "+f"(d[3])
                 : "r"(a[0]), "r"(a[1]), "r"(a[2]), "r"(a[3]), "r"(b[0]), "r"(b[1]));
}

// load a 128-row x 128-byte tile (bf16, gmem row stride 1024B) into swizzled smem
__device__ __forceinline__ void ld_tile(uint32_t sdst, const char* gsrc, int tid) {
    #pragma unroll
    for (int i = 0; i < 4; i++) {
        int chunk = tid + i * 256;          // 0..1023
        int row = chunk >> 3;               // 0..127
        int cb  = (chunk & 7) << 4;         // 16B unit within 128B row
        uint32_t sad = (sdst + row * 128 + cb) ^ ((row & 7) << 4);
        cp_async16(sad, gsrc + row * 1024 + cb);
    }
}

// ===================== kernels =====================
__global__ void k_zero() {
    int idx = blockIdx.x * blockDim.x + threadIdx.x;
    if (idx < BSZ)  g_rowsum[idx] = 0.0f;
    if (idx < NCLS) g_cls_cnt[idx] = 0;
    if (idx == 0) { g_loss = 0.0; g_npair = 0; }
}

__global__ void k_prep(const float2* __restrict__ e2, const int* __restrict__ lab) {
    int idx = blockIdx.x * blockDim.x + threadIdx.x;  // BSZ*DDIM/2 threads
    reinterpret_cast<__nv_bfloat162*>(g_ebf)[idx] = __float22bfloat162_rn(e2[idx]);
    if (idx < BSZ) {
        int c = lab[idx];
        if ((unsigned)c < NCLS) atomicAdd(&g_cls_cnt[c], 1);
    }
}

// ---- main fused GEMM + masked-exp rowsum + pair capture ----
__global__ void __launch_bounds__(256, 2)
k_gemm_rowsum(const int* __restrict__ lab) {
    extern __shared__ __align__(1024) char dsm[];   // 2 x (16KB A + 16KB B)
    __shared__ int labM[128], labN[128];

    const int tid  = threadIdx.x;
    const int lane = tid & 31;
    const int wid  = tid >> 5;
    const int wm   = wid >> 2;                    // 0..1 (m position)
    const int wn   = wid & 3;                     // 0..3 (n position)

    // decode upper-triangular tile (by <= bx)
    int t = blockIdx.x, by = 0;
    while (t >= NTILE - by) { t -= NTILE - by; by++; }
    const int bx = by + t;

    if (tid < 128) {
        labM[tid] = lab[by * 128 + tid];
        labN[tid] = lab[bx * 128 + tid];
    }

    const uint32_t sbase = smem_u32(dsm);
    const char* gA = (const char*)g_ebf + (size_t)by * 128 * 1024;
    const char* gB = (const char*)g_ebf + (size_t)bx * 128 * 1024;

    // prefetch bk=0 into buffer 0
    ld_tile(sbase,         gA, tid);
    ld_tile(sbase + 16384, gB, tid);
    asm volatile("cp.async.commit_group;" ::: "memory");

    float acc[4][4][4];
    #pragma unroll
    for (int a = 0; a < 4; a++)
        #pragma unroll
        for (int b = 0; b < 4; b++)
            #pragma unroll
            for (int c = 0; c < 4; c++) acc[a][b][c] = 0.0f;

    const int l15 = lane & 15;
    const uint32_t xm = (lane & 7) << 4;          // swizzle XOR (row&7 == lane&7 for frags)
    uint32_t aoff[4], boff[4];
    #pragma unroll
    for (int mf = 0; mf < 4; mf++)
        aoff[mf] = (uint32_t)((wm * 64 + mf * 16 + l15) * 128 + ((lane >> 4) << 4));
    #pragma unroll
    for (int nf = 0; nf < 4; nf++)
        boff[nf] = (uint32_t)((wn * 32 + nf * 8 + (l15 & 7)) * 128 + (((l15 >> 3) & 1) << 4));

    for (int bk = 0; bk < 8; bk++) {
        if (bk + 1 < 8) {
            uint32_t sb2 = sbase + ((bk + 1) & 1) * 32768;
            ld_tile(sb2,         gA + (bk + 1) * 128, tid);
            ld_tile(sb2 + 16384, gB + (bk + 1) * 128, tid);
        }
        asm volatile("cp.async.commit_group;" ::: "memory");
        asm volatile("cp.async.wait_group 1;" ::: "memory");
        __syncthreads();

        const uint32_t sa = sbase + (bk & 1) * 32768;
        const uint32_t sb = sa + 16384;
        #pragma unroll
        for (int kk = 0; kk < 4; kk++) {
            uint32_t afr[4][4], bfr[4][2];
            #pragma unroll
            for (int mf = 0; mf < 4; mf++)
                ldsm_x4(afr[mf], (sa + aoff[mf] + kk * 32) ^ xm);
            #pragma unroll
            for (int nf = 0; nf < 4; nf++)
                ldsm_x2(bfr[nf], (sb + boff[nf] + kk * 32) ^ xm);
            #pragma unroll
            for (int mf = 0; mf < 4; mf++)
                #pragma unroll
                for (int nf = 0; nf < 4; nf++)
                    mma16816(acc[mf][nf], afr[mf], bfr[nf]);
        }
        __syncthreads();
    }

    // ---------------- epilogue ----------------
    const int g  = lane >> 2;                     // row group 0..7
    const int q4 = lane & 3;                      // col group 0..3
    int rl[8], cl[8];
    #pragma unroll
    for (int mf = 0; mf < 4; mf++) {
        rl[2 * mf]     = labM[wm * 64 + mf * 16 + g];
        rl[2 * mf + 1] = labM[wm * 64 + mf * 16 + 8 + g];
    }
    #pragma unroll
    for (int nf = 0; nf < 4; nf++) {
        cl[2 * nf]     = labN[wn * 32 + nf * 8 + q4 * 2];
        cl[2 * nf + 1] = labN[wn * 32 + nf * 8 + q4 * 2 + 1];
    }

    float rp[8], cp_[8];
    #pragma unroll
    for (int z = 0; z < 8; z++) { rp[z] = 0.0f; cp_[z] = 0.0f; }

    #pragma unroll
    for (int mf = 0; mf < 4; mf++) {
        const int i0 = by * 128 + wm * 64 + mf * 16 + g;
        const int i1 = i0 + 8;
        #pragma unroll
        for (int nf = 0; nf < 4; nf++) {
            const int j0 = bx * 128 + wn * 32 + nf * 8 + q4 * 2;
            const int j1 = j0 + 1;
            const float v0 = acc[mf][nf][0], v1 = acc[mf][nf][1];
            const float v2 = acc[mf][nf][2], v3 = acc[mf][nf][3];
            const bool m00 = (rl[2*mf]   == cl[2*nf]);
            const bool m01 = (rl[2*mf]   == cl[2*nf+1]);
            const bool m10 = (rl[2*mf+1] == cl[2*nf]);
            const bool m11 = (rl[2*mf+1] == cl[2*nf+1]);
            const float e00 = m00 ? 0.0f : fast_ex2(fmaf(v0, C1F, -C2F));
            const float e01 = m01 ? 0.0f : fast_ex2(fmaf(v1, C1F, -C2F));
            const float e10 = m10 ? 0.0f : fast_ex2(fmaf(v2, C1F, -C2F));
            const float e11 = m11 ? 0.0f : fast_ex2(fmaf(v3, C1F, -C2F));
            rp[2*mf]   += e00 + e01;
            rp[2*mf+1] += e10 + e11;
            cp_[2*nf]  += e00 + e10;
            cp_[2*nf+1]+= e01 + e11;
            // pair capture (same label, strict upper triangle)
            if (m00 && j0 > i0) { int s = atomicAdd(&g_npair, 1); if (s < PAIR_CAP) { g_pk[s] = ((uint32_t)i0 << 13) | (uint32_t)j0; g_pl[s] = v0; } }
            if (m01 && j1 > i0) { int s = atomicAdd(&g_npair, 1); if (s < PAIR_CAP) { g_pk[s] = ((uint32_t)i0 << 13) | (uint32_t)j1; g_pl[s] = v1; } }
            if (m10 && j0 > i1) { int s = atomicAdd(&g_npair, 1); if (s < PAIR_CAP) { g_pk[s] = ((uint32_t)i1 << 13) | (uint32_t)j0; g_pl[s] = v2; } }
            if (m11 && j1 > i1) { int s = atomicAdd(&g_npair, 1); if (s < PAIR_CAP) { g_pk[s] = ((uint32_t)i1 << 13) | (uint32_t)j1; g_pl[s] = v3; } }
        }
    }

    // row reduction: combine lanes with same row (lane&3 varies)
    #pragma unroll
    for (int z = 0; z < 8; z++) {
        rp[z] += __shfl_xor_sync(0xffffffff, rp[z], 1);
        rp[z] += __shfl_xor_sync(0xffffffff, rp[z], 2);
    }
    if (q4 == 0) {
        #pragma unroll
        for (int mf = 0; mf < 4; mf++) {
            atomicAdd(&g_rowsum[by * 128 + wm * 64 + mf * 16 + g],     rp[2*mf]);
            atomicAdd(&g_rowsum[by * 128 + wm * 64 + mf * 16 + 8 + g], rp[2*mf+1]);
        }
    }
    // column reduction (off-diagonal tiles only; columns are rows by symmetry)
    if (bx != by) {
        #pragma unroll
        for (int z = 0; z < 8; z++) {
            cp_[z] += __shfl_xor_sync(0xffffffff, cp_[z], 4);
            cp_[z] += __shfl_xor_sync(0xffffffff, cp_[z], 8);
            cp_[z] += __shfl_xor_sync(0xffffffff, cp_[z], 16);
        }
        if (lane < 4) {
            #pragma unroll
            for (int nf = 0; nf < 4; nf++) {
                atomicAdd(&g_rowsum[bx * 128 + wn * 32 + nf * 8 + lane * 2],     cp_[2*nf]);
                atomicAdd(&g_rowsum[bx * 128 + wn * 32 + nf * 8 + lane * 2 + 1], cp_[2*nf+1]);
            }
        }
    }
}

__global__ void k_base(const int* __restrict__ lab) {
    int i = blockIdx.x * blockDim.x + threadIdx.x;
    if (i >= BSZ) return;
    g_basev[i] = logf(g_rowsum[i]) + SHIFT;
    int c = lab[i];
    int cnt = ((unsigned)c < NCLS) ? g_cls_cnt[c] : 1;
    g_invc[i] = (cnt > 1) ? 1.0f / (float)(cnt - 1) : 0.0f;
}

__global__ void k_pairs() {
    int n = g_npair; if (n > PAIR_CAP) n = PAIR_CAP;
    float lsum = 0.0f;
    for (int s = blockIdx.x * blockDim.x + threadIdx.x; s < n; s += gridDim.x * blockDim.x) {
        uint32_t pk = g_pk[s];
        float l = g_pl[s] * INV_T;
        int i = pk >> 13, j = pk & 8191;
        lsum += log1pf(__expf(g_basev[i] - l)) * g_invc[i]
              + log1pf(__expf(g_basev[j] - l)) * g_invc[j];
    }
    // block reduce
    #pragma unroll
    for (int o = 16; o; o >>= 1) lsum += __shfl_xor_sync(0xffffffff, lsum, o);
    __shared__ float ws[8];
    if ((threadIdx.x & 31) == 0) ws[threadIdx.x >> 5] = lsum;
    __syncthreads();
    if (threadIdx.x == 0) {
        float tot = 0.0f;
        #pragma unroll
        for (int w = 0; w < 8; w++) tot += ws[w];
        if (tot != 0.0f) atomicAdd(&g_loss, (double)tot);
    }
}

__global__ void k_finalize(float* out) {
    out[0] = (float)(g_loss / (double)BSZ);
}

// ===================== launch =====================
extern "C" void kernel_launch(void* const* d_in, const int* in_sizes, int n_in,
                              void* d_out, int out_size) {
    const float* embeds = (const float*)d_in[0];   // (8192, 512) fp32
    const int*   labels = (const int*)d_in[1];     // (8192,) int32 (JAX demotes int64)
    float* out = (float*)d_out;

    cudaFuncSetAttribute(k_gemm_rowsum, cudaFuncAttributeMaxDynamicSharedMemorySize, 65536);

    k_zero<<<(BSZ + 255) / 256, 256>>>();
    k_prep<<<(BSZ * DDIM / 2) / 1024, 1024>>>((const float2*)embeds, labels);
    k_gemm_rowsum<<<NTILE * (NTILE + 1) / 2, 256, 65536>>>(labels);
    k_base<<<(BSZ + 255) / 256, 256>>>(labels);
    k_pairs<<<512, 256>>>();
    k_finalize<<<1, 1>>>(out);
}

// round 5
// speedup vs baseline: 1.1483x; 1.1483x over previous
#include <cuda_runtime.h>
#include <cuda_bf16.h>
#include <cstdint>

// ===================== problem constants =====================
#define BSZ   8192
#define DDIM  512
#define NCLS  100
#define INV_T 14.285714285714286f   // 1/0.07
#define SHIFT 14.285714285714286f   // max possible logit (|e|=1)
#define LOG2E 1.4426950408889634f
#define C1F   (INV_T * LOG2E)
#define C2F   (SHIFT * LOG2E)

#define NTILE 64                    // 8192 / 128
#define PAIR_CAP (1 << 22)          // 4M pair records (expected ~331k)
#define SPAIR_CAP 1024              // per-CTA smem pair buffer

// ===================== device scratch (no allocs allowed) =====================
__device__ uint4    g_ebf_raw[BSZ * DDIM * 2 / 16];   // 8 MB bf16 embeddings (16B aligned)
#define g_ebf ((__nv_bfloat16*)g_ebf_raw)
__device__ float    g_rowsum[BSZ];
__device__ float    g_basev[BSZ];
__device__ float    g_invc[BSZ];
__device__ double   g_loss;
__device__ int      g_cls_cnt[NCLS];
__device__ int      g_npair;
__device__ uint32_t g_pk[PAIR_CAP];           // (i<<13)|j, i<j, same label
__device__ float    g_pl[PAIR_CAP];           // raw dot for that pair

// ===================== small helpers =====================
__device__ __forceinline__ uint32_t smem_u32(const void* p) {
    uint32_t a;
    asm("{ .reg .u64 t; cvta.to.shared.u64 t, %1; cvt.u32.u64 %0, t; }" : "=r"(a) : "l"(p));
    return a;
}
__device__ __forceinline__ float fast_ex2(float x) {
    float y; asm("ex2.approx.ftz.f32 %0, %1;" : "=f"(y) : "f"(x)); return y;
}
__device__ __forceinline__ void cp_async16(uint32_t sad, const void* gad) {
    asm volatile("cp.async.cg.shared.global [%0], [%1], 16;" :: "r"(sad), "l"(gad) : "memory");
}
__device__ __forceinline__ void ldsm_x4(uint32_t* r, uint32_t addr) {
    asm volatile("ldmatrix.sync.aligned.m8n8.x4.shared.b16 {%0,%1,%2,%3}, [%4];"
                 : "=r"(r[0]), "=r"(r[1]), "=r"(r[2]), "=r"(r[3]) : "r"(addr));
}
__device__ __forceinline__ void ldsm_x2(uint32_t* r, uint32_t addr) {
    asm volatile("ldmatrix.sync.aligned.m8n8.x2.shared.b16 {%0,%1}, [%2];"
                 : "=r"(r[0]), "=r"(r[1]) : "r"(addr));
}
__device__ __forceinline__ void mma16816(float* d, const uint32_t* a, const uint32_t* b) {
    asm volatile("mma.sync.aligned.m16n8k16.row.col.f32.bf16.bf16.f32 "
                 "{%0,%1,%2,%3}, {%4,%5,%6,%7}, {%8,%9}, {%0,%1,%2,%3};"
                 : "+f"(d[0]), "+f"(d[1]), "+f"(d[2]), "+f"(d[3])
                 : "r"(a[0]), "r"(a[1]), "r"(a[2]), "r"(a[3]), "r"(b[0]), "r"(b[1]));
}

// load a 128-row x 128-byte tile (bf16, gmem row stride 1024B) into swizzled smem
__device__ __forceinline__ void ld_tile(uint32_t sdst, const char* gsrc, int tid) {
    #pragma unroll
    for (int i = 0; i < 4; i++) {
        int chunk = tid + i * 256;          // 0..1023
        int row = chunk >> 3;               // 0..127
        int cb  = (chunk & 7) << 4;         // 16B unit within 128B row
        uint32_t sad = (sdst + row * 128 + cb) ^ ((row & 7) << 4);
        cp_async16(sad, gsrc + row * 1024 + cb);
    }
}

// ===================== kernels =====================
__global__ void k_zero() {
    int idx = blockIdx.x * blockDim.x + threadIdx.x;
    if (idx < BSZ)  g_rowsum[idx] = 0.0f;
    if (idx < NCLS) g_cls_cnt[idx] = 0;
    if (idx == 0) { g_loss = 0.0; g_npair = 0; }
}

__global__ void k_prep(const float2* __restrict__ e2, const int* __restrict__ lab) {
    int idx = blockIdx.x * blockDim.x + threadIdx.x;  // BSZ*DDIM/2 threads
    reinterpret_cast<__nv_bfloat162*>(g_ebf)[idx] = __float22bfloat162_rn(e2[idx]);
    if (idx < BSZ) {
        int c = lab[idx];
        if ((unsigned)c < NCLS) atomicAdd(&g_cls_cnt[c], 1);
    }
}

// positioned BEFORE the gemm so ncu's fixed capture slot lands on the gemm
__global__ void k_invc(const int* __restrict__ lab) {
    int i = blockIdx.x * blockDim.x + threadIdx.x;
    if (i >= BSZ) return;
    int c = lab[i];
    int cnt = ((unsigned)c < NCLS) ? g_cls_cnt[c] : 1;
    g_invc[i] = (cnt > 1) ? 1.0f / (float)(cnt - 1) : 0.0f;
}

// ---- main fused GEMM + masked-exp rowsum + pair capture ----
__global__ void __launch_bounds__(256, 2)
k_gemm_rowsum(const int* __restrict__ lab) {
    extern __shared__ __align__(1024) char dsm[];   // 2 x (16KB A + 16KB B)
    __shared__ int labM[128], labN[128];
    __shared__ int s_cnt, s_base;
    __shared__ uint32_t s_pk[SPAIR_CAP];
    __shared__ float    s_pl[SPAIR_CAP];

    const int tid  = threadIdx.x;
    const int lane = tid & 31;
    const int wid  = tid >> 5;
    const int wm   = wid >> 2;                    // 0..1 (m position)
    const int wn   = wid & 3;                     // 0..3 (n position)

    // decode upper-triangular tile (by <= bx)
    int t = blockIdx.x, by = 0;
    while (t >= NTILE - by) { t -= NTILE - by; by++; }
    const int bx = by + t;

    if (tid < 128) {
        labM[tid] = lab[by * 128 + tid];
        labN[tid] = lab[bx * 128 + tid];
    }
    if (tid == 0) s_cnt = 0;

    const uint32_t sbase = smem_u32(dsm);
    const char* gA = (const char*)g_ebf + (size_t)by * 128 * 1024;
    const char* gB = (const char*)g_ebf + (size_t)bx * 128 * 1024;

    // prefetch bk=0 into buffer 0
    ld_tile(sbase,         gA, tid);
    ld_tile(sbase + 16384, gB, tid);
    asm volatile("cp.async.commit_group;" ::: "memory");

    float acc[4][4][4];
    #pragma unroll
    for (int a = 0; a < 4; a++)
        #pragma unroll
        for (int b = 0; b < 4; b++)
            #pragma unroll
            for (int c = 0; c < 4; c++) acc[a][b][c] = 0.0f;

    const int l15 = lane & 15;
    const uint32_t xm = (lane & 7) << 4;          // swizzle XOR (row&7 == lane&7 for frags)
    uint32_t aoff[4], boff[4];
    #pragma unroll
    for (int mf = 0; mf < 4; mf++)
        aoff[mf] = (uint32_t)((wm * 64 + mf * 16 + l15) * 128 + ((lane >> 4) << 4));
    #pragma unroll
    for (int nf = 0; nf < 4; nf++)
        boff[nf] = (uint32_t)((wn * 32 + nf * 8 + (l15 & 7)) * 128 + (((l15 >> 3) & 1) << 4));

    for (int bk = 0; bk < 8; bk++) {
        if (bk + 1 < 8) {
            uint32_t sb2 = sbase + ((bk + 1) & 1) * 32768;
            ld_tile(sb2,         gA + (bk + 1) * 128, tid);
            ld_tile(sb2 + 16384, gB + (bk + 1) * 128, tid);
        }
        asm volatile("cp.async.commit_group;" ::: "memory");
        asm volatile("cp.async.wait_group 1;" ::: "memory");
        __syncthreads();

        const uint32_t sa = sbase + (bk & 1) * 32768;
        const uint32_t sb = sa + 16384;
        #pragma unroll
        for (int kk = 0; kk < 4; kk++) {
            uint32_t afr[4][4], bfr[4][2];
            #pragma unroll
            for (int mf = 0; mf < 4; mf++)
                ldsm_x4(afr[mf], (sa + aoff[mf] + kk * 32) ^ xm);
            #pragma unroll
            for (int nf = 0; nf < 4; nf++)
                ldsm_x2(bfr[nf], (sb + boff[nf] + kk * 32) ^ xm);
            #pragma unroll
            for (int mf = 0; mf < 4; mf++)
                #pragma unroll
                for (int nf = 0; nf < 4; nf++)
                    mma16816(acc[mf][nf], afr[mf], bfr[nf]);
        }
        __syncthreads();
    }

    // ---------------- epilogue ----------------
    const int g  = lane >> 2;                     // row group 0..7
    const int q4 = lane & 3;                      // col group 0..3
    int rl[8], cl[8];
    #pragma unroll
    for (int mf = 0; mf < 4; mf++) {
        rl[2 * mf]     = labM[wm * 64 + mf * 16 + g];
        rl[2 * mf + 1] = labM[wm * 64 + mf * 16 + 8 + g];
    }
    #pragma unroll
    for (int nf = 0; nf < 4; nf++) {
        cl[2 * nf]     = labN[wn * 32 + nf * 8 + q4 * 2];
        cl[2 * nf + 1] = labN[wn * 32 + nf * 8 + q4 * 2 + 1];
    }

    float rp[8], cp_[8];
    #pragma unroll
    for (int z = 0; z < 8; z++) { rp[z] = 0.0f; cp_[z] = 0.0f; }

    #pragma unroll
    for (int mf = 0; mf < 4; mf++) {
        const int i0 = by * 128 + wm * 64 + mf * 16 + g;
        const int i1 = i0 + 8;
        #pragma unroll
        for (int nf = 0; nf < 4; nf++) {
            const int j0 = bx * 128 + wn * 32 + nf * 8 + q4 * 2;
            const int j1 = j0 + 1;
            const float v0 = acc[mf][nf][0], v1 = acc[mf][nf][1];
            const float v2 = acc[mf][nf][2], v3 = acc[mf][nf][3];
            const bool m00 = (rl[2*mf]   == cl[2*nf]);
            const bool m01 = (rl[2*mf]   == cl[2*nf+1]);
            const bool m10 = (rl[2*mf+1] == cl[2*nf]);
            const bool m11 = (rl[2*mf+1] == cl[2*nf+1]);
            const float e00 = m00 ? 0.0f : fast_ex2(fmaf(v0, C1F, -C2F));
            const float e01 = m01 ? 0.0f : fast_ex2(fmaf(v1, C1F, -C2F));
            const float e10 = m10 ? 0.0f : fast_ex2(fmaf(v2, C1F, -C2F));
            const float e11 = m11 ? 0.0f : fast_ex2(fmaf(v3, C1F, -C2F));
            rp[2*mf]   += e00 + e01;
            rp[2*mf+1] += e10 + e11;
            cp_[2*nf]  += e00 + e10;
            cp_[2*nf+1]+= e01 + e11;
            // pair capture (same label, strict upper triangle) -> smem buffer
            if (m00 && j0 > i0) { int s = atomicAdd(&s_cnt, 1); if (s < SPAIR_CAP) { s_pk[s] = ((uint32_t)i0 << 13) | (uint32_t)j0; s_pl[s] = v0; } else { int d = atomicAdd(&g_npair, 1); if (d < PAIR_CAP) { g_pk[d] = ((uint32_t)i0 << 13) | (uint32_t)j0; g_pl[d] = v0; } } }
            if (m01 && j1 > i0) { int s = atomicAdd(&s_cnt, 1); if (s < SPAIR_CAP) { s_pk[s] = ((uint32_t)i0 << 13) | (uint32_t)j1; s_pl[s] = v1; } else { int d = atomicAdd(&g_npair, 1); if (d < PAIR_CAP) { g_pk[d] = ((uint32_t)i0 << 13) | (uint32_t)j1; g_pl[d] = v1; } } }
            if (m10 && j0 > i1) { int s = atomicAdd(&s_cnt, 1); if (s < SPAIR_CAP) { s_pk[s] = ((uint32_t)i1 << 13) | (uint32_t)j0; s_pl[s] = v2; } else { int d = atomicAdd(&g_npair, 1); if (d < PAIR_CAP) { g_pk[d] = ((uint32_t)i1 << 13) | (uint32_t)j0; g_pl[d] = v2; } } }
            if (m11 && j1 > i1) { int s = atomicAdd(&s_cnt, 1); if (s < SPAIR_CAP) { s_pk[s] = ((uint32_t)i1 << 13) | (uint32_t)j1; s_pl[s] = v3; } else { int d = atomicAdd(&g_npair, 1); if (d < PAIR_CAP) { g_pk[d] = ((uint32_t)i1 << 13) | (uint32_t)j1; g_pl[d] = v3; } } }
        }
    }

    // row reduction: combine lanes with same row (lane&3 varies)
    #pragma unroll
    for (int z = 0; z < 8; z++) {
        rp[z] += __shfl_xor_sync(0xffffffff, rp[z], 1);
        rp[z] += __shfl_xor_sync(0xffffffff, rp[z], 2);
    }
    if (q4 == 0) {
        #pragma unroll
        for (int mf = 0; mf < 4; mf++) {
            atomicAdd(&g_rowsum[by * 128 + wm * 64 + mf * 16 + g],     rp[2*mf]);
            atomicAdd(&g_rowsum[by * 128 + wm * 64 + mf * 16 + 8 + g], rp[2*mf+1]);
        }
    }
    // column reduction (off-diagonal tiles only; columns are rows by symmetry)
    if (bx != by) {
        #pragma unroll
        for (int z = 0; z < 8; z++) {
            cp_[z] += __shfl_xor_sync(0xffffffff, cp_[z], 4);
            cp_[z] += __shfl_xor_sync(0xffffffff, cp_[z], 8);
            cp_[z] += __shfl_xor_sync(0xffffffff, cp_[z], 16);
        }
        if (lane < 4) {
            #pragma unroll
            for (int nf = 0; nf < 4; nf++) {
                atomicAdd(&g_rowsum[bx * 128 + wn * 32 + nf * 8 + lane * 2],     cp_[2*nf]);
                atomicAdd(&g_rowsum[bx * 128 + wn * 32 + nf * 8 + lane * 2 + 1], cp_[2*nf+1]);
            }
        }
    }

    // flush smem pair buffer with ONE global atomic per CTA + coalesced stores
    __syncthreads();
    if (tid == 0) {
        int n = s_cnt; if (n > SPAIR_CAP) n = SPAIR_CAP;
        s_base = atomicAdd(&g_npair, n);
        s_cnt = n;
    }
    __syncthreads();
    for (int s = tid; s < s_cnt; s += 256) {
        int d = s_base + s;
        if (d < PAIR_CAP) { g_pk[d] = s_pk[s]; g_pl[d] = s_pl[s]; }
    }
}

__global__ void k_base() {
    int i = blockIdx.x * blockDim.x + threadIdx.x;
    if (i >= BSZ) return;
    g_basev[i] = logf(g_rowsum[i]) + SHIFT;
}

__global__ void k_pairs() {
    int n = g_npair; if (n > PAIR_CAP) n = PAIR_CAP;
    float lsum = 0.0f;
    for (int s = blockIdx.x * blockDim.x + threadIdx.x; s < n; s += gridDim.x * blockDim.x) {
        uint32_t pk = g_pk[s];
        float l = g_pl[s] * INV_T;
        int i = pk >> 13, j = pk & 8191;
        lsum += log1pf(__expf(g_basev[i] - l)) * g_invc[i]
              + log1pf(__expf(g_basev[j] - l)) * g_invc[j];
    }
    // block reduce
    #pragma unroll
    for (int o = 16; o; o >>= 1) lsum += __shfl_xor_sync(0xffffffff, lsum, o);
    __shared__ float ws[8];
    if ((threadIdx.x & 31) == 0) ws[threadIdx.x >> 5] = lsum;
    __syncthreads();
    if (threadIdx.x == 0) {
        float tot = 0.0f;
        #pragma unroll
        for (int w = 0; w < 8; w++) tot += ws[w];
        if (tot != 0.0f) atomicAdd(&g_loss, (double)tot);
    }
}

__global__ void k_finalize(float* out) {
    out[0] = (float)(g_loss / (double)BSZ);
}

// ===================== launch =====================
extern "C" void kernel_launch(void* const* d_in, const int* in_sizes, int n_in,
                              void* d_out, int out_size) {
    const float* embeds = (const float*)d_in[0];   // (8192, 512) fp32
    const int*   labels = (const int*)d_in[1];     // (8192,) int32 (JAX demotes int64)
    float* out = (float*)d_out;

    cudaFuncSetAttribute(k_gemm_rowsum, cudaFuncAttributeMaxDynamicSharedMemorySize, 65536);

    k_zero<<<(BSZ + 255) / 256, 256>>>();
    k_prep<<<(BSZ * DDIM / 2) / 1024, 1024>>>((const float2*)embeds, labels);
    k_invc<<<(BSZ + 255) / 256, 256>>>(labels);
    k_gemm_rowsum<<<NTILE * (NTILE + 1) / 2, 256, 65536>>>(labels);   // ncu -s 5 lands here
    k_base<<<(BSZ + 255) / 256, 256>>>();
    k_pairs<<<512, 256>>>();
    k_finalize<<<1, 1>>>(out);
}

// round 7
// speedup vs baseline: 1.5195x; 1.3233x over previous
#include <cuda_runtime.h>
#include <cuda_bf16.h>
#include <cstdint>

// ===================== problem constants =====================
#define BSZ   8192
#define DDIM  512
#define NCLS  100
#define INV_T 14.285714285714286f
#define SHIFT 14.285714285714286f
#define LOG2E 1.4426950408889634f
#define C1F   (INV_T * LOG2E)
#define C2F   (SHIFT * LOG2E)

#define NTILE 64                    // parent 128x128 tiles per dim
#define PAIR_CAP (1 << 22)
#define SPAIR_CAP 512               // per-CTA smem pair buffer

// ===================== device scratch =====================
__device__ uint4    g_ebf_raw[BSZ * DDIM * 2 / 16];   // 8 MB bf16, 16B aligned
#define g_ebf ((__nv_bfloat16*)g_ebf_raw)
__device__ float    g_rowsum[BSZ];
__device__ float    g_basev[BSZ];
__device__ float    g_invc[BSZ];
__device__ double   g_loss;
__device__ int      g_cls_cnt[NCLS];
__device__ int      g_npair;
__device__ uint32_t g_pk[PAIR_CAP];
__device__ float    g_pl[PAIR_CAP];

// ===================== helpers =====================
__device__ __forceinline__ uint32_t smem_u32(const void* p) {
    uint32_t a;
    asm("{ .reg .u64 t; cvta.to.shared.u64 t, %1; cvt.u32.u64 %0, t; }" : "=r"(a) : "l"(p));
    return a;
}
__device__ __forceinline__ float fast_ex2(float x) {
    float y; asm("ex2.approx.ftz.f32 %0, %1;" : "=f"(y) : "f"(x)); return y;
}
__device__ __forceinline__ void cp_async16(uint32_t sad, const void* gad) {
    asm volatile("cp.async.cg.shared.global [%0], [%1], 16;" :: "r"(sad), "l"(gad) : "memory");
}
__device__ __forceinline__ void ldsm_x4(uint32_t* r, uint32_t addr) {
    asm volatile("ldmatrix.sync.aligned.m8n8.x4.shared.b16 {%0,%1,%2,%3}, [%4];"
                 : "=r"(r[0]), "=r"(r[1]), "=r"(r[2]), "=r"(r[3]) : "r"(addr));
}
__device__ __forceinline__ void mma16816(float* d, const uint32_t* a, const uint32_t* b) {
    asm volatile("mma.sync.aligned.m16n8k16.row.col.f32.bf16.bf16.f32 "
                 "{%0,%1,%2,%3}, {%4,%5,%6,%7}, {%8,%9}, {%0,%1,%2,%3};"
                 : "+f"(d[0]), "+f"(d[1]), "+f"(d[2]), "+f"(d[3])
                 : "r"(a[0]), "r"(a[1]), "r"(a[2]), "r"(a[3]), "r"(b[0]), "r"(b[1]));
}

// 128-thread tile loaders: rows x 128B slabs (gmem row stride 1024B), XOR-swizzled
__device__ __forceinline__ void ld_tileA(uint32_t sdst, const char* gsrc, int tid) {
    #pragma unroll
    for (int i = 0; i < 8; i++) {                  // 128 rows * 8 chunks
        int chunk = tid + i * 128;
        int row = chunk >> 3, cb = (chunk & 7) << 4;
        uint32_t sad = (sdst + row * 128 + cb) ^ ((row & 7) << 4);
        cp_async16(sad, gsrc + row * 1024 + cb);
    }
}
__device__ __forceinline__ void ld_tileB(uint32_t sdst, const char* gsrc, int tid) {
    #pragma unroll
    for (int i = 0; i < 4; i++) {                  // 64 rows * 8 chunks
        int chunk = tid + i * 128;
        int row = chunk >> 3, cb = (chunk & 7) << 4;
        uint32_t sad = (sdst + row * 128 + cb) ^ ((row & 7) << 4);
        cp_async16(sad, gsrc + row * 1024 + cb);
    }
}

// ===================== kernels =====================
__global__ void k_zero() {
    int idx = blockIdx.x * blockDim.x + threadIdx.x;
    if (idx < BSZ)  g_rowsum[idx] = 0.0f;
    if (idx < NCLS) g_cls_cnt[idx] = 0;
    if (idx == 0) { g_loss = 0.0; g_npair = 0; }
}

__global__ void k_prep(const float2* __restrict__ e2, const int* __restrict__ lab) {
    int idx = blockIdx.x * blockDim.x + threadIdx.x;
    reinterpret_cast<__nv_bfloat162*>(g_ebf)[idx] = __float22bfloat162_rn(e2[idx]);
    if (idx < BSZ) {
        int c = lab[idx];
        if ((unsigned)c < NCLS) atomicAdd(&g_cls_cnt[c], 1);
    }
}

__global__ void k_invc(const int* __restrict__ lab) {
    int i = blockIdx.x * blockDim.x + threadIdx.x;
    if (i >= BSZ) return;
    int c = lab[i];
    int cnt = ((unsigned)c < NCLS) ? g_cls_cnt[c] : 1;
    g_invc[i] = (cnt > 1) ? 1.0f / (float)(cnt - 1) : 0.0f;
}

// ---- fused GEMM(128x64 per CTA) + masked-exp rowsum + pair capture ----
__global__ void __launch_bounds__(128, 4)
k_gemm_rowsum(const int* __restrict__ lab) {
    extern __shared__ __align__(1024) char dsm[];   // 2 stages x (16KB A + 8KB B)
    __shared__ int labM[128], labN[64];
    __shared__ int s_cnt, s_base;
    __shared__ uint32_t s_pk[SPAIR_CAP];
    __shared__ float    s_pl[SPAIR_CAP];

    const int tid  = threadIdx.x;
    const int lane = tid & 31;
    const int wid  = tid >> 5;
    const int wm   = wid >> 1;          // 0..1
    const int wn   = wid & 1;           // 0..1

    // parent tile decode (by <= bx), 2 CTAs per parent (N halves)
    int pid = blockIdx.x >> 1;
    const int half = blockIdx.x & 1;
    int by = 0;
    while (pid >= NTILE - by) { pid -= NTILE - by; by++; }
    const int bx = by + pid;
    const bool offd = (bx != by);
    const int ib = by * 128;
    const int jb = bx * 128 + half * 64;

    if (tid < 128) labM[tid] = lab[ib + tid];
    if (tid < 64)  labN[tid] = lab[jb + tid];
    if (tid == 0)  s_cnt = 0;

    const uint32_t sbase = smem_u32(dsm);
    const char* gA = (const char*)g_ebf + (size_t)ib * 1024;
    const char* gB = (const char*)g_ebf + (size_t)jb * 1024;

    ld_tileA(sbase,         gA, tid);
    ld_tileB(sbase + 16384, gB, tid);
    asm volatile("cp.async.commit_group;" ::: "memory");

    float acc[4][4][4];
    #pragma unroll
    for (int a = 0; a < 4; a++)
        #pragma unroll
        for (int b = 0; b < 4; b++)
            #pragma unroll
            for (int c = 0; c < 4; c++) acc[a][b][c] = 0.0f;

    const int l15 = lane & 15;
    const uint32_t xm = (lane & 7) << 4;
    uint32_t aoff[4], boffp[2];
    #pragma unroll
    for (int mf = 0; mf < 4; mf++)
        aoff[mf] = (uint32_t)((wm * 64 + mf * 16 + l15) * 128 + ((lane >> 4) << 4));
    #pragma unroll
    for (int p = 0; p < 2; p++)
        boffp[p] = (uint32_t)((wn * 32 + p * 16 + ((lane >> 4) << 3) + (lane & 7)) * 128
                              + (((lane >> 3) & 1) << 4));

    for (int bk = 0; bk < 8; bk++) {
        if (bk + 1 < 8) {
            uint32_t s2 = sbase + ((bk + 1) & 1) * 24576;
            ld_tileA(s2,         gA + (bk + 1) * 128, tid);
            ld_tileB(s2 + 16384, gB + (bk + 1) * 128, tid);
        }
        asm volatile("cp.async.commit_group;" ::: "memory");
        asm volatile("cp.async.wait_group 1;" ::: "memory");
        __syncthreads();

        const uint32_t sa = sbase + (bk & 1) * 24576;
        const uint32_t sb = sa + 16384;
        #pragma unroll
        for (int kk = 0; kk < 4; kk++) {
            uint32_t afr[4][4], bq[2][4];
            #pragma unroll
            for (int mf = 0; mf < 4; mf++)
                ldsm_x4(afr[mf], (sa + aoff[mf] + kk * 32) ^ xm);
            #pragma unroll
            for (int p = 0; p < 2; p++)
                ldsm_x4(bq[p], (sb + boffp[p] + kk * 32) ^ xm);
            #pragma unroll
            for (int mf = 0; mf < 4; mf++)
                #pragma unroll
                for (int nf = 0; nf < 4; nf++)
                    mma16816(acc[mf][nf], afr[mf], &bq[nf >> 1][(nf & 1) * 2]);
        }
        __syncthreads();
    }

    // ---------------- epilogue ----------------
    const int g  = lane >> 2;
    const int q4 = lane & 3;
    int rl[8], cl[8];
    #pragma unroll
    for (int mf = 0; mf < 4; mf++) {
        rl[2*mf]   = labM[wm * 64 + mf * 16 + g];
        rl[2*mf+1] = labM[wm * 64 + mf * 16 + 8 + g];
    }
    #pragma unroll
    for (int nf = 0; nf < 4; nf++) {
        cl[2*nf]   = labN[wn * 32 + nf * 8 + q4 * 2];
        cl[2*nf+1] = labN[wn * 32 + nf * 8 + q4 * 2 + 1];
    }

    float rp[8], cp_[8];
    #pragma unroll
    for (int z = 0; z < 8; z++) { rp[z] = 0.0f; cp_[z] = 0.0f; }

    #pragma unroll
    for (int mf = 0; mf < 4; mf++) {
        const int i0 = ib + wm * 64 + mf * 16 + g;
        const int i1 = i0 + 8;
        #pragma unroll
        for (int nf = 0; nf < 4; nf++) {
            const int j0 = jb + wn * 32 + nf * 8 + q4 * 2;
            const int j1 = j0 + 1;
            const float v0 = acc[mf][nf][0], v1 = acc[mf][nf][1];
            const float v2 = acc[mf][nf][2], v3 = acc[mf][nf][3];
            const bool m00 = (rl[2*mf]   == cl[2*nf]);
            const bool m01 = (rl[2*mf]   == cl[2*nf+1]);
            const bool m10 = (rl[2*mf+1] == cl[2*nf]);
            const bool m11 = (rl[2*mf+1] == cl[2*nf+1]);
            const float e00 = m00 ? 0.0f : fast_ex2(fmaf(v0, C1F, -C2F));
            const float e01 = m01 ? 0.0f : fast_ex2(fmaf(v1, C1F, -C2F));
            const float e10 = m10 ? 0.0f : fast_ex2(fmaf(v2, C1F, -C2F));
            const float e11 = m11 ? 0.0f : fast_ex2(fmaf(v3, C1F, -C2F));
            rp[2*mf]   += e00 + e01;
            rp[2*mf+1] += e10 + e11;
            cp_[2*nf]  += e00 + e10;
            cp_[2*nf+1]+= e01 + e11;
            if (m00 | m01 | m10 | m11) {            // rare (~1% of quads)
                #define PUSH(I, J, V) do { \
                    int s_ = atomicAdd(&s_cnt, 1); \
                    if (s_ < SPAIR_CAP) { s_pk[s_] = ((uint32_t)(I) << 13) | (uint32_t)(J); s_pl[s_] = (V); } \
                    else { int d_ = atomicAdd(&g_npair, 1); \
                           if (d_ < PAIR_CAP) { g_pk[d_] = ((uint32_t)(I) << 13) | (uint32_t)(J); g_pl[d_] = (V); } } \
                } while (0)
                if (m00 && (offd || j0 > i0)) PUSH(i0, j0, v0);
                if (m01 && (offd || j1 > i0)) PUSH(i0, j1, v1);
                if (m10 && (offd || j0 > i1)) PUSH(i1, j0, v2);
                if (m11 && (offd || j1 > i1)) PUSH(i1, j1, v3);
                #undef PUSH
            }
        }
    }

    // row sums: reduce over q4 (lane bits 0-1)
    #pragma unroll
    for (int z = 0; z < 8; z++) {
        rp[z] += __shfl_xor_sync(0xffffffff, rp[z], 1);
        rp[z] += __shfl_xor_sync(0xffffffff, rp[z], 2);
    }
    if (q4 == 0) {
        #pragma unroll
        for (int mf = 0; mf < 4; mf++) {
            atomicAdd(&g_rowsum[ib + wm * 64 + mf * 16 + g],     rp[2*mf]);
            atomicAdd(&g_rowsum[ib + wm * 64 + mf * 16 + 8 + g], rp[2*mf+1]);
        }
    }
    // column sums (off-diagonal parents only): reduce over g (lane bits 2-4)
    if (offd) {
        #pragma unroll
        for (int z = 0; z < 8; z++) {
            cp_[z] += __shfl_xor_sync(0xffffffff, cp_[z], 4);
            cp_[z] += __shfl_xor_sync(0xffffffff, cp_[z], 8);
            cp_[z] += __shfl_xor_sync(0xffffffff, cp_[z], 16);
        }
        if (lane < 4) {
            #pragma unroll
            for (int nf = 0; nf < 4; nf++) {
                atomicAdd(&g_rowsum[jb + wn * 32 + nf * 8 + lane * 2],     cp_[2*nf]);
                atomicAdd(&g_rowsum[jb + wn * 32 + nf * 8 + lane * 2 + 1], cp_[2*nf+1]);
            }
        }
    }

    // flush pair buffer: one global atomic per CTA
    __syncthreads();
    if (tid == 0) {
        int n = s_cnt; if (n > SPAIR_CAP) n = SPAIR_CAP;
        s_base = atomicAdd(&g_npair, n);
        s_cnt = n;
    }
    __syncthreads();
    for (int s = tid; s < s_cnt; s += 128) {
        int d = s_base + s;
        if (d < PAIR_CAP) { g_pk[d] = s_pk[s]; g_pl[d] = s_pl[s]; }
    }
}

__global__ void k_base() {
    int i = blockIdx.x * blockDim.x + threadIdx.x;
    if (i >= BSZ) return;
    g_basev[i] = logf(g_rowsum[i]) + SHIFT;
}

__global__ void k_pairs() {
    int n = g_npair; if (n > PAIR_CAP) n = PAIR_CAP;
    float lsum = 0.0f;
    for (int s = blockIdx.x * blockDim.x + threadIdx.x; s < n; s += gridDim.x * blockDim.x) {
        uint32_t pk = g_pk[s];
        float l = g_pl[s] * INV_T;
        int i = pk >> 13, j = pk & 8191;
        lsum += log1pf(__expf(g_basev[i] - l)) * g_invc[i]
              + log1pf(__expf(g_basev[j] - l)) * g_invc[j];
    }
    #pragma unroll
    for (int o = 16; o; o >>= 1) lsum += __shfl_xor_sync(0xffffffff, lsum, o);
    __shared__ float ws[8];
    if ((threadIdx.x & 31) == 0) ws[threadIdx.x >> 5] = lsum;
    __syncthreads();
    if (threadIdx.x == 0) {
        float tot = 0.0f;
        #pragma unroll
        for (int w = 0; w < 8; w++) tot += ws[w];
        if (tot != 0.0f) atomicAdd(&g_loss, (double)tot);
    }
}

__global__ void k_finalize(float* out) {
    out[0] = (float)(g_loss / (double)BSZ);
}

// ===================== launch =====================
extern "C" void kernel_launch(void* const* d_in, const int* in_sizes, int n_in,
                              void* d_out, int out_size) {
    const float* embeds = (const float*)d_in[0];
    const int*   labels = (const int*)d_in[1];
    float* out = (float*)d_out;

    cudaFuncSetAttribute(k_gemm_rowsum, cudaFuncAttributeMaxDynamicSharedMemorySize, 49152);

    k_zero<<<(BSZ + 255) / 256, 256>>>();
    k_prep<<<(BSZ * DDIM / 2) / 1024, 1024>>>((const float2*)embeds, labels);
    k_invc<<<(BSZ + 255) / 256, 256>>>(labels);
    k_gemm_rowsum<<<NTILE * (NTILE + 1), 128, 49152>>>(labels);   // 2 CTAs per parent tile
    k_base<<<(BSZ + 255) / 256, 256>>>();
    k_pairs<<<512, 256>>>();
    k_finalize<<<1, 1>>>(out);
}